// round 3
// baseline (speedup 1.0000x reference)
#include <cuda_runtime.h>
#include <cuda_bf16.h>

// Fast Walsh-Hadamard transform, 16384 rows x 1024 fp32.
// y[row] = FWHT(x[row]) / 32, emitted as interleaved (real, 0) pairs.
//
// One warp per row, 32 values per thread. Lane l owns elements
// {2l + b + 64j : b in {0,1}, j in 0..15}:
//   stride 1            -> register butterfly (b pair)
//   strides 2..32       -> 5 shfl.xor stages (lane bits)
//   strides 64..512     -> register butterflies over j
// No shared memory, no barriers. Loads are 16 coalesced LDG.64 (MLP=16),
// stores are 16 perfectly coalesced STG.128 with zeros folded in.

#define DIMN 1024
#define WPB  8          // warps (=rows) per block -> 256 threads

__device__ __forceinline__ void bf(float &x, float &y) {
    float s = x + y;
    y = x - y;
    x = s;
}

__global__ void __launch_bounds__(32 * WPB, 4)
fwht_kernel(const float2* __restrict__ xin, float4* __restrict__ yout, int nrows)
{
    const int l   = threadIdx.x & 31;
    const int w   = threadIdx.x >> 5;
    const int row = blockIdx.x * WPB + w;
    if (row >= nrows) return;

    float a[16], b[16];

    // ---- 16 independent coalesced LDG.64, front-batched ----
    const float2* in = xin + (size_t)row * (DIMN / 2) + l;
    #pragma unroll
    for (int j = 0; j < 16; j++) {
        float2 p = in[32 * j];
        a[j] = p.x;            // element 2l   + 64j
        b[j] = p.y;            // element 2l+1 + 64j
    }

    // ---- stride 1 (register, b-pair) ----
    #pragma unroll
    for (int j = 0; j < 16; j++) bf(a[j], b[j]);

    // ---- strides 2,4,8,16,32 via shfl.xor on lane bits ----
    #pragma unroll
    for (int d = 1; d <= 16; d <<= 1) {
        const bool up = (l & d) != 0;
        #pragma unroll
        for (int j = 0; j < 16; j++) {
            float oa = __shfl_xor_sync(0xffffffffu, a[j], d);
            float ob = __shfl_xor_sync(0xffffffffu, b[j], d);
            a[j] = up ? (oa - a[j]) : (a[j] + oa);
            b[j] = up ? (ob - b[j]) : (b[j] + ob);
        }
    }

    // ---- strides 64,128,256,512: butterflies over j bits ----
    #pragma unroll
    for (int s = 1; s <= 8; s <<= 1) {
        #pragma unroll
        for (int j = 0; j < 16; j++) {
            if ((j & s) == 0) {
                bf(a[j], a[j + s]);
                bf(b[j], b[j + s]);
            }
        }
    }

    // ---- scaled, interleaved (real, 0) stores; 16 coalesced STG.128 ----
    const float sc = 0.03125f;   // 1/sqrt(1024)
    float4* out = yout + (size_t)row * (2 * DIMN / 4) + l;
    #pragma unroll
    for (int j = 0; j < 16; j++) {
        __stcs(out + 32 * j, make_float4(a[j] * sc, 0.0f, b[j] * sc, 0.0f));
    }
}

extern "C" void kernel_launch(void* const* d_in, const int* in_sizes, int n_in,
                              void* d_out, int out_size)
{
    const float* x = (const float*)d_in[0];   // [B, S, 1024] fp32
    // d_in[1] is H; unused — the transform is computed directly.
    float* out = (float*)d_out;               // [B, S, 1024, 2] fp32

    const int nrows = in_sizes[0] / DIMN;     // 16384
    const int grid  = (nrows + WPB - 1) / WPB;

    fwht_kernel<<<grid, 32 * WPB>>>((const float2*)x, (float4*)out, nrows);
}